// round 8
// baseline (speedup 1.0000x reference)
#include <cuda_runtime.h>
#include <cuda_bf16.h>
#include <math.h>
#include <stdint.h>

#define KDIM    4096
#define H1      50
#define H2      32
#define CIN     100
#define BR      32
#define KC      32
#define NTHREADS 256

__global__ void zero_fill_kernel(float* __restrict__ out, long long n) {
    long long i = (long long)blockIdx.x * blockDim.x + threadIdx.x;
    if (i < n) out[i] = 0.f;
}

struct Ptrs {
    const void *state, *hidden, *W1, *b1, *W2, *b2, *Wh, *bh, *Wo, *bo;
};

__device__ __forceinline__ float rdf(const void* p, long long i, bool bf) {
    return bf ? __bfloat162float(((const __nv_bfloat16*)p)[i])
              : ((const float*)p)[i];
}

__global__ __launch_bounds__(NTHREADS, 2)
void net_fused_kernel(Ptrs P,
                      void* __restrict__ out_base, int sig_limit,
                      int write_hidden, int batch)
{
    // ---- dtype autodetect from first 128 bytes of state (uniform result) ---
    bool bf;
    {
        const uint32_t* w = (const uint32_t*)P.state;
        int cnt = 0;
        #pragma unroll
        for (int i = 0; i < 32; i++) {
            uint16_t m = (uint16_t)(w[i] & 0x7FFFu);
            if (m == 0u || (m >= 0x3000u && m <= 0x4200u)) cnt++;
        }
        bf = (cnt >= 20);
    }

    __shared__ float sC[BR][CIN + 4];
    __shared__ float sU[KC*(BR+1) + KC*(H1+2)];
    __shared__ float sW2[CIN * H2];
    __shared__ float sWh[H2 * H1];
    __shared__ float sb1[H1], sbh[H1], sWo[H1], sb2[H2], sbo[1];
    float (*sA)[BR + 1] = (float(*)[BR + 1])sU;
    float (*sB)[H1 + 2] = (float(*)[H1 + 2])(sU + KC * (BR + 1));
    float (*sL2)[H2]    = (float(*)[H2])sU;

    const int tid  = threadIdx.x;
    const int row0 = blockIdx.x * BR;
    const int tx   = tid & 15;
    const int ty   = tid >> 4;
    const int lrow = tid >> 3;
    const int lq   = tid & 7;
    const int  grow = row0 + lrow;
    const bool rok  = (grow < batch);

    for (int idx = tid; idx < CIN * H2; idx += NTHREADS) sW2[idx] = rdf(P.W2, idx, bf);
    for (int idx = tid; idx < H2 * H1; idx += NTHREADS)  sWh[idx] = rdf(P.Wh, idx, bf);
    if (tid < H1) {
        sb1[tid] = rdf(P.b1, tid, bf);
        sbh[tid] = rdf(P.bh, tid, bf);
        sWo[tid] = rdf(P.Wo, tid, bf);
    }
    if (tid < H2) sb2[tid] = rdf(P.b2, tid, bf);
    if (tid == 0) sbo[0] = rdf(P.bo, 0, bf);

    float acc[2][4] = {{0.f,0.f,0.f,0.f},{0.f,0.f,0.f,0.f}};

    // ---------------- Stage 1: level = state @ W1 ---------------------------
    for (int kb = 0; kb < KDIM; kb += KC) {
        float va0 = 0.f, va1 = 0.f, va2 = 0.f, va3 = 0.f;
        if (rok) {
            long long off = (long long)grow * KDIM + kb + 4 * lq;
            va0 = rdf(P.state, off + 0, bf);
            va1 = rdf(P.state, off + 1, bf);
            va2 = rdf(P.state, off + 2, bf);
            va3 = rdf(P.state, off + 3, bf);
        }
        __syncthreads();
        sA[4*lq + 0][lrow] = va0;
        sA[4*lq + 1][lrow] = va1;
        sA[4*lq + 2][lrow] = va2;
        sA[4*lq + 3][lrow] = va3;
        for (int idx = tid; idx < KC * (H1 + 2); idx += NTHREADS) {
            int kk = idx / (H1 + 2);
            int c  = idx % (H1 + 2);
            sB[kk][c] = (c < H1) ? rdf(P.W1, (long long)(kb + kk) * H1 + c, bf) : 0.f;
        }
        __syncthreads();
        #pragma unroll
        for (int kk = 0; kk < KC; kk++) {
            float a0 = sA[kk][ty];
            float a1 = sA[kk][ty + 16];
            #pragma unroll
            for (int j = 0; j < 4; j++) {
                float b = sB[kk][tx + 16 * j];
                acc[0][j] = fmaf(a0, b, acc[0][j]);
                acc[1][j] = fmaf(a1, b, acc[1][j]);
            }
        }
    }
    __syncthreads();

    #pragma unroll
    for (int j = 0; j < 4; j++) {
        int c = tx + 16 * j;
        if (c < H1) {
            float bb = sb1[c];
            sC[ty][c]      = acc[0][j] + bb;
            sC[ty + 16][c] = acc[1][j] + bb;
        }
    }
    for (int idx = tid; idx < BR * H1; idx += NTHREADS) {
        int r = idx / H1, c = idx % H1;
        sC[r][H1 + c] = (row0 + r < batch)
                      ? rdf(P.hidden, (long long)(row0 + r) * H1 + c, bf) : 0.f;
    }
    __syncthreads();

    // ---------------- Stage 2: combined @ W2 + b2 ---------------------------
    {
        int c2 = tid & 31;
        int rg = tid >> 5;
        float a2[4] = {0.f, 0.f, 0.f, 0.f};
        #pragma unroll 4
        for (int kk = 0; kk < CIN; kk++) {
            float w = sW2[kk * H2 + c2];
            #pragma unroll
            for (int i = 0; i < 4; i++)
                a2[i] = fmaf(sC[rg * 4 + i][kk], w, a2[i]);
        }
        float bb = sb2[c2];
        #pragma unroll
        for (int i = 0; i < 4; i++)
            sL2[rg * 4 + i][c2] = a2[i] + bb;
    }
    __syncthreads();

    // ---------------- Stage 3: level2 @ Wh + bh -----------------------------
    for (int idx = tid; idx < BR * H1; idx += NTHREADS) {
        int r = idx / H1, c = idx % H1;
        float a = sbh[c];
        #pragma unroll
        for (int kk = 0; kk < H2; kk++)
            a = fmaf(sL2[r][kk], sWh[kk * H1 + c], a);
        if (write_hidden && (row0 + r) < batch) {
            long long o = (long long)batch + (long long)(row0 + r) * H1 + c;
            if (bf) ((__nv_bfloat16*)out_base)[o] = __float2bfloat16(a);
            else    ((float*)out_base)[o] = a;
        }
        sC[r][c] = a;
    }
    __syncthreads();

    // ---------------- Stage 4: sigmoid(hn @ Wo + bo) ------------------------
    if (tid < BR && (row0 + tid) < sig_limit) {
        float a = sbo[0];
        #pragma unroll
        for (int c = 0; c < H1; c++)
            a = fmaf(sC[tid][c], sWo[c], a);
        float s = 1.f / (1.f + expf(-a));
        if (bf) ((__nv_bfloat16*)out_base)[row0 + tid] = __float2bfloat16(s);
        else    ((float*)out_base)[row0 + tid] = s;
    }
}

static bool map_inputs(const long long* s, int n_in,
                       int& i_state, int& i_hidden, int& i_W1, int& i_b1,
                       int& i_W2, int& i_b2, int& i_Wh, int& i_bh,
                       int& i_Wo, int& i_bo, long long& batch)
{
    i_state = i_hidden = i_W1 = i_W2 = i_Wh = i_b2 = i_bo = -1;
    int idx50[3] = {-1, -1, -1};
    int n50 = 0;

    long long maxs = -1;
    for (int i = 0; i < n_in; i++)
        if (s[i] > maxs) { maxs = s[i]; i_state = i; }
    if (i_state < 0 || maxs <= 0 || (maxs % KDIM) != 0) return false;
    batch = maxs / KDIM;
    if (batch <= 0) return false;

    for (int i = 0; i < n_in; i++) {
        if (i == i_state) continue;
        long long v = s[i];
        if      (v == (long long)KDIM * H1) i_W1 = i;
        else if (v == batch * H1)           i_hidden = i;
        else if (v == (long long)CIN * H2)  i_W2 = i;
        else if (v == (long long)H2 * H1)   i_Wh = i;
        else if (v == H2)                   i_b2 = i;
        else if (v == 1)                    i_bo = i;
        else if (v == H1) { if (n50 < 3) idx50[n50] = i; n50++; }
    }
    if (i_hidden < 0 || i_W1 < 0 || i_W2 < 0 || i_Wh < 0 ||
        i_b2 < 0 || i_bo < 0 || n50 != 3) return false;

    if (idx50[0] == i_Wh + 1) { i_Wo = idx50[0]; i_b1 = idx50[1]; i_bh = idx50[2]; }
    else                      { i_b1 = idx50[0]; i_bh = idx50[1]; i_Wo = idx50[2]; }
    return true;
}

extern "C" void kernel_launch(void* const* d_in, const int* in_sizes, int n_in,
                              void* d_out, int out_size) {
    long long se[32];
    int n = (n_in < 32) ? n_in : 32;
    for (int i = 0; i < n; i++) se[i] = in_sizes[i];

    int i_state, i_hidden, i_W1, i_b1, i_W2, i_b2, i_Wh, i_bh, i_Wo, i_bo;
    long long batch = 0;
    bool ok = map_inputs(se, n, i_state, i_hidden, i_W1, i_b1, i_W2, i_b2,
                         i_Wh, i_bh, i_Wo, i_bo, batch);

    if (!ok || batch > (1 << 24)) {
        if (out_size > 0)
            zero_fill_kernel<<<(out_size + 255) / 256, 256>>>((float*)d_out,
                                                              (long long)out_size);
        return;
    }

    Ptrs P;
    P.state = d_in[i_state];  P.hidden = d_in[i_hidden];
    P.W1 = d_in[i_W1];  P.b1 = d_in[i_b1];
    P.W2 = d_in[i_W2];  P.b2 = d_in[i_b2];
    P.Wh = d_in[i_Wh];  P.bh = d_in[i_bh];
    P.Wo = d_in[i_Wo];  P.bo = d_in[i_bo];

    int ibatch       = (int)batch;
    int sig_limit    = (out_size < ibatch) ? out_size : ibatch;
    int write_hidden = ((long long)out_size >= batch * (1 + H1)) ? 1 : 0;

    int nblocks = (ibatch + BR - 1) / BR;
    net_fused_kernel<<<nblocks, NTHREADS>>>(P, d_out, sig_limit,
                                            write_hidden, ibatch);
}

// round 10
// speedup vs baseline: 3.5919x; 3.5919x over previous
#include <cuda_runtime.h>
#include <cuda_bf16.h>
#include <math.h>
#include <stdint.h>

#define KDIM 4096
#define H1   50
#define H2   32
#define CIN  100
#define NPAD 64          // N padded for tensor tiles
#define MT   64          // M rows per block
#define KC   32          // K chunk per mainloop iter
#define NT   256         // threads per block

#define A_PITCH 40       // bf16 elems per A smem row (80B, conflict-free ldmatrix)
#define B_PITCH 72       // bf16 elems per B smem row (144B, conflict-free ldmatrix)

// Pre-split W1 (fp32 -> bf16 hi/lo), padded to NPAD cols. 1 MB __device__ scratch.
__device__ __nv_bfloat16 g_W1hi[KDIM * NPAD];
__device__ __nv_bfloat16 g_W1lo[KDIM * NPAD];

struct Ptrs {
    const void *state, *hidden, *W1, *b1, *W2, *b2, *Wh, *bh, *Wo, *bo;
};

__device__ __forceinline__ float rdf(const void* p, long long i, bool bf) {
    return bf ? __bfloat162float(((const __nv_bfloat16*)p)[i])
              : ((const float*)p)[i];
}

// dtype autodetect from first 128 bytes of state (uniform, proven in R8)
__device__ __forceinline__ bool detect_bf(const void* state) {
    const uint32_t* w = (const uint32_t*)state;
    int cnt = 0;
    #pragma unroll
    for (int i = 0; i < 32; i++) {
        uint16_t m = (uint16_t)(w[i] & 0x7FFFu);
        if (m == 0u || (m >= 0x3000u && m <= 0x4200u)) cnt++;
    }
    return (cnt >= 20);
}

__device__ __forceinline__ uint32_t smem_u32(const void* p) {
    return (uint32_t)__cvta_generic_to_shared(p);
}

__device__ __forceinline__ void ldsm_x4(uint32_t (&r)[4], uint32_t addr) {
    asm volatile("ldmatrix.sync.aligned.m8n8.x4.shared.b16 {%0,%1,%2,%3}, [%4];"
                 : "=r"(r[0]), "=r"(r[1]), "=r"(r[2]), "=r"(r[3]) : "r"(addr));
}
__device__ __forceinline__ void ldsm_x4_t(uint32_t (&r)[4], uint32_t addr) {
    asm volatile("ldmatrix.sync.aligned.m8n8.x4.trans.shared.b16 {%0,%1,%2,%3}, [%4];"
                 : "=r"(r[0]), "=r"(r[1]), "=r"(r[2]), "=r"(r[3]) : "r"(addr));
}
__device__ __forceinline__ void mma_bf16(float (&d)[4], const uint32_t (&a)[4],
                                         uint32_t b0, uint32_t b1) {
    asm volatile(
        "mma.sync.aligned.m16n8k16.row.col.f32.bf16.bf16.f32 "
        "{%0,%1,%2,%3}, {%4,%5,%6,%7}, {%8,%9}, {%0,%1,%2,%3};"
        : "+f"(d[0]), "+f"(d[1]), "+f"(d[2]), "+f"(d[3])
        : "r"(a[0]), "r"(a[1]), "r"(a[2]), "r"(a[3]), "r"(b0), "r"(b1));
}

__global__ void zero_fill_kernel(float* __restrict__ out, long long n) {
    long long i = (long long)blockIdx.x * blockDim.x + threadIdx.x;
    if (i < n) out[i] = 0.f;
}

// ---- Prep: split W1 fp32 -> (hi, lo) bf16, pad n to 64 with zeros -----------
__global__ void prep_w1_kernel(const void* __restrict__ W1,
                               const void* __restrict__ state) {
    const bool bf = detect_bf(state);
    int i = blockIdx.x * blockDim.x + threadIdx.x;
    if (i >= KDIM * NPAD) return;
    int k = i >> 6;          // /64
    int n = i & 63;
    float v = (n < H1) ? rdf(W1, (long long)k * H1 + n, bf) : 0.f;
    __nv_bfloat16 hi = __float2bfloat16(v);
    __nv_bfloat16 lo = __float2bfloat16(v - __bfloat162float(hi));
    g_W1hi[i] = hi;
    g_W1lo[i] = lo;
}

// ---- Main fused kernel ------------------------------------------------------
__global__ __launch_bounds__(NT, 1)
void net_tc_kernel(Ptrs P, void* __restrict__ out_base, int sig_limit,
                   int write_hidden, int batch)
{
    const bool bf = detect_bf(P.state);

    // Union: stage-1 bf16 tiles  |  stage-2+ fp32 buffers
    __shared__ __align__(16) unsigned char sraw[MT * 104 * 4 + MT * 33 * 4]; // 35072B
    __nv_bfloat16* sAhi = (__nv_bfloat16*)sraw;              // [64][A_PITCH]
    __nv_bfloat16* sAlo = sAhi + MT * A_PITCH;
    __nv_bfloat16* sBhi = sAlo + MT * A_PITCH;               // [32][B_PITCH]
    __nv_bfloat16* sBlo = sBhi + KC * B_PITCH;
    float* sC  = (float*)sraw;                               // [64][104]
    float* sL2 = (float*)(sraw + MT * 104 * 4);              // [64][33]

    const int tid    = threadIdx.x;
    const int lane   = tid & 31;
    const int wid    = tid >> 5;
    const int warp_m = wid & 3;          // 0..3 -> 16-row subtile
    const int warp_n = wid >> 2;         // 0..1 -> 32-col group
    const int m0     = warp_m * 16;
    const int n0w    = warp_n * 32;

    const int row0 = blockIdx.x * MT;

    // staging maps
    const int ar = tid >> 2;             // 0..63 : A row
    const int ac = (tid & 3) * 8;        // col group of 8
    const bool arok = (row0 + ar) < batch;
    const int bk = tid >> 3;             // 0..31 : B k-row
    const int bn = (tid & 7) * 8;        // col group of 8

    // ldmatrix per-lane bases
    const int l_r = lane & 7, l_g = lane >> 3;
    const int a_row  = m0 + l_r + ((l_g & 1) << 3);
    const int a_koff = (l_g & 2) << 2;                       // 0 or 8
    const uint32_t sAhi_u = smem_u32(sAhi);
    const uint32_t sAlo_u = smem_u32(sAlo);
    const uint32_t ahi_base = sAhi_u + (a_row * A_PITCH + a_koff) * 2;
    const uint32_t alo_base = sAlo_u + (a_row * A_PITCH + a_koff) * 2;
    const int b_k    = lane & 15;
    const int b_noff = (lane >> 4) << 3;                     // 0 or 8
    const uint32_t bhi_base = smem_u32(sBhi) + (b_k * B_PITCH + n0w + b_noff) * 2;
    const uint32_t blo_base = smem_u32(sBlo) + (b_k * B_PITCH + n0w + b_noff) * 2;

    float d[4][4];                                           // 4 n-tiles x 4
    #pragma unroll
    for (int t = 0; t < 4; t++)
        #pragma unroll
        for (int j = 0; j < 4; j++) d[t][j] = 0.f;

    // staging registers
    float aS[8];
    uint4 bHi, bLo;

    // ---- prologue: load chunk 0 ----
    {
        long long off = (long long)(row0 + ar) * KDIM + 0 + ac;
        if (arok) {
            if (bf) {
                #pragma unroll
                for (int j = 0; j < 8; j++) aS[j] = rdf(P.state, off + j, true);
            } else {
                float4 v0 = *(const float4*)((const float*)P.state + off);
                float4 v1 = *(const float4*)((const float*)P.state + off + 4);
                aS[0]=v0.x; aS[1]=v0.y; aS[2]=v0.z; aS[3]=v0.w;
                aS[4]=v1.x; aS[5]=v1.y; aS[6]=v1.z; aS[7]=v1.w;
            }
        } else {
            #pragma unroll
            for (int j = 0; j < 8; j++) aS[j] = 0.f;
        }
        bHi = *(const uint4*)&g_W1hi[(long long)bk * NPAD + bn];
        bLo = *(const uint4*)&g_W1lo[(long long)bk * NPAD + bn];
    }

    // ---- mainloop ----
    for (int kb = 0; kb < KDIM; kb += KC) {
        __syncthreads();   // smem free (consumers of previous chunk done)

        // split A and store hi/lo (one uint4 each; 16B aligned: pitch 80B)
        {
            uint32_t hv[4], lv[4];
            #pragma unroll
            for (int j = 0; j < 4; j++) {
                __nv_bfloat16 h0 = __float2bfloat16(aS[2*j]);
                __nv_bfloat16 h1 = __float2bfloat16(aS[2*j+1]);
                __nv_bfloat16 l0 = __float2bfloat16(aS[2*j]   - __bfloat162float(h0));
                __nv_bfloat16 l1 = __float2bfloat16(aS[2*j+1] - __bfloat162float(h1));
                hv[j] = (uint32_t)*(uint16_t*)&h0 | ((uint32_t)*(uint16_t*)&h1 << 16);
                lv[j] = (uint32_t)*(uint16_t*)&l0 | ((uint32_t)*(uint16_t*)&l1 << 16);
            }
            *(uint4*)&sAhi[ar * A_PITCH + ac] = make_uint4(hv[0], hv[1], hv[2], hv[3]);
            *(uint4*)&sAlo[ar * A_PITCH + ac] = make_uint4(lv[0], lv[1], lv[2], lv[3]);
        }
        // store B (pitch 144B = 16*9, aligned)
        *(uint4*)&sBhi[bk * B_PITCH + bn] = bHi;
        *(uint4*)&sBlo[bk * B_PITCH + bn] = bLo;

        __syncthreads();   // smem ready

        // issue next chunk's global loads (overlap with mma)
        int kn = kb + KC;
        if (kn < KDIM) {
            long long off = (long long)(row0 + ar) * KDIM + kn + ac;
            if (arok) {
                if (bf) {
                    #pragma unroll
                    for (int j = 0; j < 8; j++) aS[j] = rdf(P.state, off + j, true);
                } else {
                    float4 v0 = *(const float4*)((const float*)P.state + off);
                    float4 v1 = *(const float4*)((const float*)P.state + off + 4);
                    aS[0]=v0.x; aS[1]=v0.y; aS[2]=v0.z; aS[3]=v0.w;
                    aS[4]=v1.x; aS[5]=v1.y; aS[6]=v1.z; aS[7]=v1.w;
                }
            }
            bHi = *(const uint4*)&g_W1hi[(long long)kn * NPAD + bk * NPAD + bn];
            bLo = *(const uint4*)&g_W1lo[(long long)kn * NPAD + bk * NPAD + bn];
        }

        // mma: 2 k16 steps x (3 split passes x 4 n-tiles)
        #pragma unroll
        for (int ks = 0; ks < 2; ks++) {
            uint32_t Ah[4], Al[4], Bh0[4], Bh1[4], Bl0[4], Bl1[4];
            ldsm_x4  (Ah,  ahi_base + ks * 32);            // +16 elems * 2B
            ldsm_x4  (Al,  alo_base + ks * 32);
            ldsm_x4_t(Bh0, bhi_base + ks * (16 * B_PITCH * 2));
            ldsm_x4_t(Bh1, bhi_base + ks * (16 * B_PITCH * 2) + 32);
            ldsm_x4_t(Bl0, blo_base + ks * (16 * B_PITCH * 2));
            ldsm_x4_t(Bl1, blo_base + ks * (16 * B_PITCH * 2) + 32);

            mma_bf16(d[0], Ah, Bh0[0], Bh0[1]);
            mma_bf16(d[1], Ah, Bh0[2], Bh0[3]);
            mma_bf16(d[2], Ah, Bh1[0], Bh1[1]);
            mma_bf16(d[3], Ah, Bh1[2], Bh1[3]);

            mma_bf16(d[0], Ah, Bl0[0], Bl0[1]);
            mma_bf16(d[1], Ah, Bl0[2], Bl0[3]);
            mma_bf16(d[2], Ah, Bl1[0], Bl1[1]);
            mma_bf16(d[3], Ah, Bl1[2], Bl1[3]);

            mma_bf16(d[0], Al, Bh0[0], Bh0[1]);
            mma_bf16(d[1], Al, Bh0[2], Bh0[3]);
            mma_bf16(d[2], Al, Bh1[0], Bh1[1]);
            mma_bf16(d[3], Al, Bh1[2], Bh1[3]);
        }
    }
    __syncthreads();   // all warps done reading stage-1 smem

    // ---- epilogue: level + b1 -> sC[:,0:50] --------------------------------
    {
        int cr = lane >> 2;            // 0..7
        int cc = (lane & 3) * 2;       // 0,2,4,6
        #pragma unroll
        for (int t = 0; t < 4; t++) {
            int colb = n0w + t * 8 + cc;
            #pragma unroll
            for (int j = 0; j < 4; j++) {
                int row = m0 + cr + ((j >> 1) << 3);   // +8 for c2,c3
                int col = colb + (j & 1);
                if (col < H1)
                    sC[row * 104 + col] = d[t][j] + rdf(P.b1, col, bf);
            }
        }
    }
    // hidden -> sC[:,50:100]
    for (int idx = tid; idx < MT * H1; idx += NT) {
        int r = idx / H1, c = idx % H1;
        sC[r * 104 + H1 + c] = (row0 + r < batch)
            ? rdf(P.hidden, (long long)(row0 + r) * H1 + c, bf) : 0.f;
    }
    __syncthreads();

    // ---- stage 2: combined @ W2 + b2 (100 -> 32) ---------------------------
    {
        int c2 = lane;                 // output col
        int rg = wid;                  // rows rg*8 .. +7
        float a2[8];
        #pragma unroll
        for (int i = 0; i < 8; i++) a2[i] = 0.f;
        for (int kk = 0; kk < CIN; kk++) {
            float w = rdf(P.W2, kk * H2 + c2, bf);
            #pragma unroll
            for (int i = 0; i < 8; i++)
                a2[i] = fmaf(sC[(rg * 8 + i) * 104 + kk], w, a2[i]);
        }
        float bb = rdf(P.b2, c2, bf);
        #pragma unroll
        for (int i = 0; i < 8; i++)
            sL2[(rg * 8 + i) * 33 + c2] = a2[i] + bb;
    }
    __syncthreads();

    // ---- stage 3: level2 @ Wh + bh (32 -> 50) ------------------------------
    for (int idx = tid; idx < MT * H1; idx += NT) {
        int r = idx / H1, c = idx % H1;
        float a = rdf(P.bh, c, bf);
        #pragma unroll
        for (int kk = 0; kk < H2; kk++)
            a = fmaf(sL2[r * 33 + kk], rdf(P.Wh, kk * H1 + c, bf), a);
        if (write_hidden && (row0 + r) < batch) {
            long long o = (long long)batch + (long long)(row0 + r) * H1 + c;
            if (bf) ((__nv_bfloat16*)out_base)[o] = __float2bfloat16(a);
            else    ((float*)out_base)[o] = a;
        }
        sC[r * 104 + c] = a;
    }
    __syncthreads();

    // ---- stage 4: sigmoid(hn @ Wo + bo) ------------------------------------
    if (tid < MT && (row0 + tid) < sig_limit) {
        float a = rdf(P.bo, 0, bf);
        #pragma unroll
        for (int c = 0; c < H1; c++)
            a = fmaf(sC[tid * 104 + c], rdf(P.Wo, c, bf), a);
        float s = 1.f / (1.f + expf(-a));
        if (bf) ((__nv_bfloat16*)out_base)[row0 + tid] = __float2bfloat16(s);
        else    ((float*)out_base)[row0 + tid] = s;
    }
}

static bool map_inputs(const long long* s, int n_in,
                       int& i_state, int& i_hidden, int& i_W1, int& i_b1,
                       int& i_W2, int& i_b2, int& i_Wh, int& i_bh,
                       int& i_Wo, int& i_bo, long long& batch)
{
    i_state = i_hidden = i_W1 = i_W2 = i_Wh = i_b2 = i_bo = -1;
    int idx50[3] = {-1, -1, -1};
    int n50 = 0;

    long long maxs = -1;
    for (int i = 0; i < n_in; i++)
        if (s[i] > maxs) { maxs = s[i]; i_state = i; }
    if (i_state < 0 || maxs <= 0 || (maxs % KDIM) != 0) return false;
    batch = maxs / KDIM;
    if (batch <= 0) return false;

    for (int i = 0; i < n_in; i++) {
        if (i == i_state) continue;
        long long v = s[i];
        if      (v == (long long)KDIM * H1) i_W1 = i;
        else if (v == batch * H1)           i_hidden = i;
        else if (v == (long long)CIN * H2)  i_W2 = i;
        else if (v == (long long)H2 * H1)   i_Wh = i;
        else if (v == H2)                   i_b2 = i;
        else if (v == 1)                    i_bo = i;
        else if (v == H1) { if (n50 < 3) idx50[n50] = i; n50++; }
    }
    if (i_hidden < 0 || i_W1 < 0 || i_W2 < 0 || i_Wh < 0 ||
        i_b2 < 0 || i_bo < 0 || n50 != 3) return false;

    if (idx50[0] == i_Wh + 1) { i_Wo = idx50[0]; i_b1 = idx50[1]; i_bh = idx50[2]; }
    else                      { i_b1 = idx50[0]; i_bh = idx50[1]; i_Wo = idx50[2]; }
    return true;
}

extern "C" void kernel_launch(void* const* d_in, const int* in_sizes, int n_in,
                              void* d_out, int out_size) {
    long long se[32];
    int n = (n_in < 32) ? n_in : 32;
    for (int i = 0; i < n; i++) se[i] = in_sizes[i];

    int i_state, i_hidden, i_W1, i_b1, i_W2, i_b2, i_Wh, i_bh, i_Wo, i_bo;
    long long batch = 0;
    bool ok = map_inputs(se, n, i_state, i_hidden, i_W1, i_b1, i_W2, i_b2,
                         i_Wh, i_bh, i_Wo, i_bo, batch);

    if (!ok || batch > (1 << 24)) {
        if (out_size > 0)
            zero_fill_kernel<<<(out_size + 255) / 256, 256>>>((float*)d_out,
                                                              (long long)out_size);
        return;
    }

    Ptrs P;
    P.state = d_in[i_state];  P.hidden = d_in[i_hidden];
    P.W1 = d_in[i_W1];  P.b1 = d_in[i_b1];
    P.W2 = d_in[i_W2];  P.b2 = d_in[i_b2];
    P.Wh = d_in[i_Wh];  P.bh = d_in[i_bh];
    P.Wo = d_in[i_Wo];  P.bo = d_in[i_bo];

    int ibatch       = (int)batch;
    int sig_limit    = (out_size < ibatch) ? out_size : ibatch;
    int write_hidden = ((long long)out_size >= batch * (1 + H1)) ? 1 : 0;

    // prep: split W1 into bf16 hi/lo scratch (deterministic, graph-capturable)
    prep_w1_kernel<<<(KDIM * NPAD + 255) / 256, 256>>>(P.W1, P.state);

    int nblocks = (ibatch + MT - 1) / MT;
    net_tc_kernel<<<nblocks, NT>>>(P, d_out, sig_limit, write_hidden, ibatch);
}